// round 15
// baseline (speedup 1.0000x reference)
#include <cuda_runtime.h>
#include <cuda_fp16.h>
#include <cstdint>

#define D 128
#define HDIM 512
#define MAXN 50048
#define LN_EPS 1e-5f

// ---------------- scratch ----------------
__device__ __half g_zh[(size_t)MAXN * D];        // z fp16 (edge gather)
__device__ float  g_w[MAXN];                     // exp(leaky_relu(z @ a)) per src node
__device__ float  g_hc[(size_t)MAXN * D];        // fp32 hc (h2 residual + LN)
__device__ __half g_hc_h[(size_t)MAXN * D];      // fp16 hc, k-permuted (h1 GEMM A)
__device__ __half g_hidden_h[(size_t)MAXN * HDIM]; // fp16 hidden, k-permuted (h2 GEMM A)
__device__ __half g_w1h[HDIM * D];               // fp16 w1, k-permuted
__device__ __half g_w2h[D * HDIM];               // fp16 w2, k-permuted
__device__ int    g_row_start[MAXN + 1];

// k-permutation within each 16-k block
__device__ __host__ __forceinline__ int kperm_src(int pos) {
    int q = pos >> 2, s = pos & 3;
    return (q << 1) + ((s >> 1) << 3) + (s & 1);
}

// ---------------- CSR offsets from sorted dst ----------------
__global__ void k_row_start(const int* __restrict__ dst, int E, int Nc) {
    int i = blockIdx.x * blockDim.x + threadIdx.x;
    if (i > E) return;
    int cur  = (i == E) ? Nc : dst[i];
    int prev = (i == 0) ? -1 : dst[i - 1];
    for (int n = prev + 1; n <= cur; n++) g_row_start[n] = i;
}

// ---------------- helpers ----------------
__device__ __forceinline__ void mma_f16(float (&c)[4],
                                        const uint32_t (&a)[4],
                                        const uint32_t (&b)[2]) {
    asm volatile(
        "mma.sync.aligned.m16n8k16.row.col.f32.f16.f16.f32 "
        "{%0,%1,%2,%3}, {%4,%5,%6,%7}, {%8,%9}, {%0,%1,%2,%3};"
        : "+f"(c[0]), "+f"(c[1]), "+f"(c[2]), "+f"(c[3])
        : "r"(a[0]), "r"(a[1]), "r"(a[2]), "r"(a[3]), "r"(b[0]), "r"(b[1]));
}
__device__ __forceinline__ void cp16(uint32_t s, const void* g, int sz) {
    asm volatile("cp.async.ca.shared.global [%0], [%1], 16, %2;" :: "r"(s), "l"(g), "r"(sz));
}
#define CP_COMMIT() asm volatile("cp.async.commit_group;")
template <int N> __device__ __forceinline__ void cp_wait() {
    asm volatile("cp.async.wait_group %0;" :: "n"(N));
}

// ---------------- weight conversion to permuted fp16 ----------------
__global__ void k_cvt_w(const float* __restrict__ w1, const float* __restrict__ w2) {
    int i = blockIdx.x * blockDim.x + threadIdx.x;
    if (i >= HDIM * D) return;
    {   // w1: [HDIM][128]
        int row = i >> 7, pos = i & 127;
        int src = (pos & ~15) + kperm_src(pos & 15);
        g_w1h[i] = __float2half_rn(w1[(row << 7) + src]);
    }
    {   // w2: [D][512]
        int row = i >> 9, pos = i & 511;
        int src = (pos & ~15) + kperm_src(pos & 15);
        g_w2h[i] = __float2half_rn(w2[(row << 9) + src]);
    }
}

// ========== fp16 convert-staging core (gemm_z): fp32 in, cvt while staging ==========
// BK=16 halves; smem row = 32B; permuted store so frags are contiguous uint2.
template <int KDIM>
__device__ __forceinline__ void mma_core_cvt_h(
    const float* __restrict__ A, const float* __restrict__ B,
    int Nrows, int row0, int col0,
    float (&acc)[2][8][4], char* As, char* Bs)
{
    const int tid  = threadIdx.x;
    const int wid  = tid >> 5, lane = tid & 31;
    const int wm = wid >> 1, wn = wid & 1;
    const int lr = lane >> 2, q8 = (lane & 3) << 3;
    const int srow = tid >> 1;
    const int skq  = (tid & 1) * 8;
    const bool va = (row0 + srow) < Nrows;
    const float* Ap = A + (size_t)(row0 + srow) * KDIM + skq;
    const float* Bp = B + (size_t)(col0 + srow) * KDIM + skq;
    const float4 f40 = make_float4(0.f, 0.f, 0.f, 0.f);
    char* asw = As + srow * 32 + (tid & 1) * 4;   // permuted pair slots, step 8B
    char* bsw = Bs + srow * 32 + (tid & 1) * 4;

    float4 pa0 = va ? *(const float4*)(Ap)     : f40;
    float4 pa1 = va ? *(const float4*)(Ap + 4) : f40;
    float4 pb0 = *(const float4*)(Bp);
    float4 pb1 = *(const float4*)(Bp + 4);

    constexpr int NT = KDIM / 16;
    #pragma unroll 1
    for (int kt = 0; kt < NT; kt++) {
        *(__half2*)(asw +  0) = __floats2half2_rn(pa0.x, pa0.y);
        *(__half2*)(asw +  8) = __floats2half2_rn(pa0.z, pa0.w);
        *(__half2*)(asw + 16) = __floats2half2_rn(pa1.x, pa1.y);
        *(__half2*)(asw + 24) = __floats2half2_rn(pa1.z, pa1.w);
        *(__half2*)(bsw +  0) = __floats2half2_rn(pb0.x, pb0.y);
        *(__half2*)(bsw +  8) = __floats2half2_rn(pb0.z, pb0.w);
        *(__half2*)(bsw + 16) = __floats2half2_rn(pb1.x, pb1.y);
        *(__half2*)(bsw + 24) = __floats2half2_rn(pb1.z, pb1.w);
        __syncthreads();

        if (kt + 1 < NT) {
            int ko = (kt + 1) * 16;
            pa0 = va ? *(const float4*)(Ap + ko)     : f40;
            pa1 = va ? *(const float4*)(Ap + ko + 4) : f40;
            pb0 = *(const float4*)(Bp + ko);
            pb1 = *(const float4*)(Bp + ko + 4);
        }
        uint32_t af[2][4];
        #pragma unroll
        for (int mf = 0; mf < 2; mf++) {
            int r = wm * 32 + mf * 16 + lr;
            uint2 lo = *(const uint2*)(As + r * 32 + q8);
            uint2 hi = *(const uint2*)(As + (r + 8) * 32 + q8);
            af[mf][0] = lo.x; af[mf][1] = hi.x;
            af[mf][2] = lo.y; af[mf][3] = hi.y;
        }
        #pragma unroll
        for (int nf = 0; nf < 8; nf++) {
            int n = wn * 64 + nf * 8 + lr;
            uint2 bv = *(const uint2*)(Bs + n * 32 + q8);
            uint32_t bf[2] = {bv.x, bv.y};
            mma_f16(acc[0][nf], af[0], bf);
            mma_f16(acc[1][nf], af[1], bf);
        }
        __syncthreads();
    }
}

// ========== fp16 pipelined core (k-permuted operands, cp.async, 3-stage) ==========
template <int KDIM>
__device__ __forceinline__ void mma_core_h(
    const __half* __restrict__ A, const __half* __restrict__ B,
    int Nrows, int row0, int col0,
    float (&acc)[2][8][4], char* SA, char* SB)
{
    const int tid  = threadIdx.x;
    const int wid  = tid >> 5, lane = tid & 31;
    const int wm = wid >> 1, wn = wid & 1;
    const int lr = lane >> 2, q8 = (lane & 3) << 3;
    const int srow = tid >> 1;
    const int sk32 = (tid & 1) << 5;
    const int swz  = ((srow >> 1) & 1) << 5;
    const int szA  = ((row0 + srow) < Nrows) ? 16 : 0;
    const __half* Ap = A + (size_t)(row0 + srow) * KDIM + (tid & 1) * 16;
    const __half* Bp = B + (size_t)(col0 + srow) * KDIM + (tid & 1) * 16;
    uint32_t sa = (uint32_t)__cvta_generic_to_shared(SA);
    uint32_t sb = (uint32_t)__cvta_generic_to_shared(SB);
    const uint32_t so0 = (uint32_t)(srow * 64 + (sk32 ^ swz));
    constexpr int NT = KDIM / 32;

    auto stage = [&](int st, int kt) {
        uint32_t ao = sa + (uint32_t)st * 8192u;
        uint32_t bo = sb + (uint32_t)st * 8192u;
        const __half* a = Ap + kt * 32;
        const __half* b = Bp + kt * 32;
        cp16(ao + so0,      a,     szA);
        cp16(ao + so0 + 16, a + 8, szA);
        cp16(bo + so0,      b,     16);
        cp16(bo + so0 + 16, b + 8, 16);
        CP_COMMIT();
    };
    stage(0, 0);
    stage(1, 1 < NT ? 1 : 0);

    #pragma unroll 1
    for (int kt = 0; kt < NT; kt++) {
        if (kt + 1 < NT) cp_wait<1>(); else cp_wait<0>();
        __syncthreads();
        if (kt + 2 < NT) stage((kt + 2) % 3, kt + 2);
        const char* as = SA + (kt % 3) * 8192;
        const char* bs = SB + (kt % 3) * 8192;
        #pragma unroll
        for (int ks = 0; ks < 2; ks++) {
            const int cb = (ks << 5) + q8;
            uint32_t af[2][4];
            #pragma unroll
            for (int mf = 0; mf < 2; mf++) {
                int r  = wm * 32 + mf * 16 + lr;
                int r2 = r + 8;
                uint2 lo = *(const uint2*)(as + r  * 64 + (cb ^ (((r  >> 1) & 1) << 5)));
                uint2 hi = *(const uint2*)(as + r2 * 64 + (cb ^ (((r2 >> 1) & 1) << 5)));
                af[mf][0] = lo.x; af[mf][1] = hi.x;
                af[mf][2] = lo.y; af[mf][3] = hi.y;
            }
            #pragma unroll
            for (int nf = 0; nf < 8; nf++) {
                int n = wn * 64 + nf * 8 + lr;
                uint2 bv = *(const uint2*)(bs + n * 64 + (cb ^ (((n >> 1) & 1) << 5)));
                uint32_t bf[2] = {bv.x, bv.y};
                mma_f16(acc[0][nf], af[0], bf);
                mma_f16(acc[1][nf], af[1], bf);
            }
        }
    }
    __syncthreads();
}

// ------- z = s @ W_fc^T (fp16 MMA, stored fp16), fused w = exp(leaky_relu(z @ a)) -------
__global__ void __launch_bounds__(256, 2)
k_gemm_z(const float* __restrict__ s, const float* __restrict__ Wfc,
         const float* __restrict__ a_attn, int Nrows) {
    __shared__ __align__(16) char As[128 * 32], Bs[128 * 32];
    __shared__ float zap[2][128];
    float acc[2][8][4] = {};
    const int row0 = blockIdx.x * 128;
    mma_core_cvt_h<D>(s, Wfc, Nrows, row0, 0, acc, As, Bs);
    const int lane = threadIdx.x & 31, wid = threadIdx.x >> 5;
    const int wm = wid >> 1, wn = wid & 1;
    const int lr = lane >> 2, lc2 = (lane & 3) * 2;
    float2 av[8];
    #pragma unroll
    for (int nf = 0; nf < 8; nf++)
        av[nf] = *(const float2*)&a_attn[wn * 64 + nf * 8 + lc2];
    #pragma unroll
    for (int mf = 0; mf < 2; mf++)
        #pragma unroll
        for (int cp = 0; cp < 2; cp++) {
            int rl = wm * 32 + mf * 16 + lr + cp * 8;
            int r  = row0 + rl;
            float p = 0.f;
            #pragma unroll
            for (int nf = 0; nf < 8; nf++) {
                float z0 = acc[mf][nf][cp * 2], z1 = acc[mf][nf][cp * 2 + 1];
                p += z0 * av[nf].x + z1 * av[nf].y;
                if (r < Nrows) {
                    *(__half2*)&g_zh[(size_t)r * D + wn * 64 + nf * 8 + lc2] =
                        __floats2half2_rn(z0, z1);
                }
            }
            p += __shfl_xor_sync(0xffffffffu, p, 1);
            p += __shfl_xor_sync(0xffffffffu, p, 2);
            if ((lane & 3) == 0) zap[wn][rl] = p;
        }
    __syncthreads();
    if (wn == 0 && (lane & 3) == 0) {
        #pragma unroll
        for (int mf = 0; mf < 2; mf++)
            #pragma unroll
            for (int cp = 0; cp < 2; cp++) {
                int rl = wm * 32 + mf * 16 + lr + cp * 8;
                int r  = row0 + rl;
                if (r < Nrows) {
                    float e = zap[0][rl] + zap[1][rl];
                    e = e > 0.f ? e : 0.01f * e;
                    g_w[r] = __expf(e);
                }
            }
    }
}

// ------- warp-per-node aggregation (fp16 z, pipelined idx prefetch) -------
__global__ void __launch_bounds__(256)
k_aggregate(const float* __restrict__ c, const int* __restrict__ src, int Nc) {
    int gw   = (blockIdx.x * blockDim.x + threadIdx.x) >> 5;
    int lane = threadIdx.x & 31;
    if (gw >= Nc) return;
    int beg = g_row_start[gw], end = g_row_start[gw + 1];
    float4 A0 = make_float4(0.f, 0.f, 0.f, 0.f);
    float4 A1 = make_float4(0.f, 0.f, 0.f, 0.f);
    float d0 = 0.f, d1 = 0.f;
    const uint2* zb = (const uint2*)g_zh + lane;   // row stride = 32 uint2
    int i = beg;
    if (i + 2 <= end) {
        int s0 = __ldg(&src[i]);
        int s1 = __ldg(&src[i + 1]);
        for (;;) {
            float w0 = g_w[s0];
            float w1 = g_w[s1];
            uint2 u0 = __ldg(zb + (size_t)s0 * 32);
            uint2 u1 = __ldg(zb + (size_t)s1 * 32);
            i += 2;
            bool more = (i + 2 <= end);
            if (more) {                      // prefetch next indices during this FMA window
                s0 = __ldg(&src[i]);
                s1 = __ldg(&src[i + 1]);
            }
            float2 l0 = __half22float2(*(const __half2*)&u0.x);
            float2 h0 = __half22float2(*(const __half2*)&u0.y);
            float2 l1 = __half22float2(*(const __half2*)&u1.x);
            float2 h1 = __half22float2(*(const __half2*)&u1.y);
            d0 += w0; d1 += w1;
            A0.x += w0 * l0.x; A0.y += w0 * l0.y; A0.z += w0 * h0.x; A0.w += w0 * h0.y;
            A1.x += w1 * l1.x; A1.y += w1 * l1.y; A1.z += w1 * h1.x; A1.w += w1 * h1.y;
            if (!more) break;
        }
    }
    if (i < end) {
        int s0 = __ldg(&src[i]);
        float w0 = g_w[s0];
        uint2 u0 = __ldg(zb + (size_t)s0 * 32);
        float2 l0 = __half22float2(*(const __half2*)&u0.x);
        float2 h0 = __half22float2(*(const __half2*)&u0.y);
        d0 += w0;
        A0.x += w0 * l0.x; A0.y += w0 * l0.y; A0.z += w0 * h0.x; A0.w += w0 * h0.y;
    }
    float4 A;
    A.x = A0.x + A1.x; A.y = A0.y + A1.y;
    A.z = A0.z + A1.z; A.w = A0.w + A1.w;
    if (beg < end) {
        float inv = 1.f / (d0 + d1);
        A.x *= inv; A.y *= inv; A.z *= inv; A.w *= inv;
    }
    float4 cv = *(const float4*)&c[(size_t)gw * D + lane * 4];
    float4 h;
    h.x = (A.x > 0.f ? A.x : __expf(A.x) - 1.f) + cv.x;
    h.y = (A.y > 0.f ? A.y : __expf(A.y) - 1.f) + cv.y;
    h.z = (A.z > 0.f ? A.z : __expf(A.z) - 1.f) + cv.z;
    h.w = (A.w > 0.f ? A.w : __expf(A.w) - 1.f) + cv.w;
    *(float4*)&g_hc[(size_t)gw * D + lane * 4] = h;
    // permuted fp16 write for the h1 GEMM A operand
    {
        int b = lane >> 2, r4 = lane & 3;
        int base1 = ((r4 & 1) << 3) | ((r4 >> 1) << 1);
        __half* dst = g_hc_h + (size_t)gw * D + b * 16;
        *(__half2*)(dst + base1)     = __floats2half2_rn(h.x, h.y);
        *(__half2*)(dst + base1 + 4) = __floats2half2_rn(h.z, h.w);
    }
}

// ---------------- hidden = relu(hc @ w1^T + b1), fp16 permuted out ----------------
__global__ void __launch_bounds__(256, 2)
k_gemm_h1(const float* __restrict__ b1, int Nrows) {
    __shared__ __align__(16) char SA[3 * 8192], SB[3 * 8192];
    float acc[2][8][4] = {};
    const int row0 = blockIdx.x * 128;
    const int col0 = blockIdx.y * 128;
    mma_core_h<D>(g_hc_h, g_w1h, Nrows, row0, col0, acc, SA, SB);
    const int lane = threadIdx.x & 31, wid = threadIdx.x >> 5;
    const int wm = wid >> 1, wn = wid & 1;
    const int lr = lane >> 2, lc2 = (lane & 3) * 2;
    float2 bb[8];
    #pragma unroll
    for (int nf = 0; nf < 8; nf++)
        bb[nf] = *(const float2*)&b1[col0 + wn * 64 + nf * 8 + lc2];
    #pragma unroll
    for (int mf = 0; mf < 2; mf++)
        #pragma unroll
        for (int cp = 0; cp < 2; cp++) {
            int r = row0 + wm * 32 + mf * 16 + lr + cp * 8;
            if (r >= Nrows) continue;
            #pragma unroll
            for (int nf = 0; nf < 8; nf++) {
                float vx = fmaxf(acc[mf][nf][cp * 2]     + bb[nf].x, 0.f);
                float vy = fmaxf(acc[mf][nf][cp * 2 + 1] + bb[nf].y, 0.f);
                int cc = col0 + wn * 64 + nf * 8 + lc2;
                int m  = (cc & 15) >> 1;
                int pp = ((m & 3) << 2) | ((m >> 2) << 1);
                *(__half2*)&g_hidden_h[(size_t)r * HDIM + (cc & ~15) + pp] =
                    __floats2half2_rn(vx, vy);
            }
        }
}

// --------- y = hidden @ w2^T + b2 + hc, LayerNorm -> out ---------
__global__ void __launch_bounds__(256, 2)
k_gemm_h2_ln(const float* __restrict__ b2,
             const float* __restrict__ lng, const float* __restrict__ lnb,
             float* __restrict__ out, int Nrows) {
    __shared__ __align__(16) char SA[3 * 8192], SB[3 * 8192];
    float acc[2][8][4] = {};
    const int row0 = blockIdx.x * 128;
    mma_core_h<HDIM>(g_hidden_h, g_w2h, Nrows, row0, 0, acc, SA, SB);
    float* part1 = (float*)SB;
    float* part2 = (float*)SB + 256;
    const int lane = threadIdx.x & 31, wid = threadIdx.x >> 5;
    const int wm = wid >> 1, wn = wid & 1;
    const int lr = lane >> 2, lc2 = (lane & 3) * 2;

    float2 bb[8], gg[8], be[8];
    #pragma unroll
    for (int nf = 0; nf < 8; nf++) {
        int cc = wn * 64 + nf * 8 + lc2;
        bb[nf] = *(const float2*)&b2[cc];
        gg[nf] = *(const float2*)&lng[cc];
        be[nf] = *(const float2*)&lnb[cc];
    }
    #pragma unroll
    for (int mf = 0; mf < 2; mf++)
        #pragma unroll
        for (int cp = 0; cp < 2; cp++) {
            int rl = wm * 32 + mf * 16 + lr + cp * 8;
            int r  = row0 + rl;
            bool ok = r < Nrows;
            float s1 = 0.f, s2 = 0.f;
            #pragma unroll
            for (int nf = 0; nf < 8; nf++) {
                float2 hv = ok ? *(const float2*)&g_hc[(size_t)r * D + wn * 64 + nf * 8 + lc2]
                               : make_float2(0.f, 0.f);
                float y0 = acc[mf][nf][cp * 2]     + bb[nf].x + hv.x;
                float y1 = acc[mf][nf][cp * 2 + 1] + bb[nf].y + hv.y;
                acc[mf][nf][cp * 2]     = y0;
                acc[mf][nf][cp * 2 + 1] = y1;
                s1 += y0 + y1;
                s2 += y0 * y0 + y1 * y1;
            }
            s1 += __shfl_xor_sync(0xffffffffu, s1, 1);
            s2 += __shfl_xor_sync(0xffffffffu, s2, 1);
            s1 += __shfl_xor_sync(0xffffffffu, s1, 2);
            s2 += __shfl_xor_sync(0xffffffffu, s2, 2);
            if ((lane & 3) == 0) {
                part1[wn * 128 + rl] = s1;
                part2[wn * 128 + rl] = s2;
            }
        }
    __syncthreads();
    #pragma unroll
    for (int mf = 0; mf < 2; mf++)
        #pragma unroll
        for (int cp = 0; cp < 2; cp++) {
            int rl = wm * 32 + mf * 16 + lr + cp * 8;
            int r  = row0 + rl;
            float s1 = part1[rl] + part1[128 + rl];
            float s2 = part2[rl] + part2[128 + rl];
            float mean = s1 * (1.f / D);
            float var  = s2 * (1.f / D) - mean * mean;
            float rstd = rsqrtf(var + LN_EPS);
            if (r >= Nrows) continue;
            #pragma unroll
            for (int nf = 0; nf < 8; nf++) {
                float2 v;
                v.x = (acc[mf][nf][cp * 2]     - mean) * rstd * gg[nf].x + be[nf].x;
                v.y = (acc[mf][nf][cp * 2 + 1] - mean) * rstd * gg[nf].y + be[nf].y;
                *(float2*)&out[(size_t)r * D + wn * 64 + nf * 8 + lc2] = v;
            }
        }
}

// ---------------- launch ----------------
extern "C" void kernel_launch(void* const* d_in, const int* in_sizes, int n_in,
                              void* d_out, int out_size) {
    const float* s      = (const float*)d_in[0];
    const float* c      = (const float*)d_in[1];
    const int*   src    = (const int*)d_in[2];
    const int*   dst    = (const int*)d_in[3];
    const float* Wfc    = (const float*)d_in[4];
    const float* a_attn = (const float*)d_in[5];
    const float* w1     = (const float*)d_in[6];
    const float* b1     = (const float*)d_in[7];
    const float* w2     = (const float*)d_in[8];
    const float* b2     = (const float*)d_in[9];
    const float* lng    = (const float*)d_in[10];
    const float* lnb    = (const float*)d_in[11];
    float* out = (float*)d_out;

    int Ns = in_sizes[0] / D;
    int Nc = in_sizes[1] / D;
    int E  = in_sizes[2];
    (void)n_in; (void)out_size;

    k_row_start<<<(E + 1 + 255) / 256, 256>>>(dst, E, Nc);
    k_cvt_w<<<(HDIM * D + 255) / 256, 256>>>(w1, w2);
    k_gemm_z<<<(Ns + 127) / 128, 256>>>(s, Wfc, a_attn, Ns);
    k_aggregate<<<(Nc * 32 + 255) / 256, 256>>>(c, src, Nc);
    {
        dim3 g((Nc + 127) / 128, HDIM / 128);
        k_gemm_h1<<<g, 256>>>(b1, Nc);
    }
    k_gemm_h2_ln<<<(Nc + 127) / 128, 256>>>(b2, lng, lnb, out, Nc);
}

// round 16
// speedup vs baseline: 1.0294x; 1.0294x over previous
#include <cuda_runtime.h>
#include <cuda_fp16.h>
#include <cstdint>

#define D 128
#define HDIM 512
#define MAXN 50048
#define LN_EPS 1e-5f

// ---------------- scratch ----------------
__device__ __half g_zh[(size_t)MAXN * D];        // z fp16 (edge gather)
__device__ float  g_w[MAXN];                     // exp(leaky_relu(z @ a)) per src node
__device__ float  g_hc[(size_t)MAXN * D];        // fp32 hc (h2 residual + LN)
__device__ __half g_hc_h[(size_t)MAXN * D];      // fp16 hc, k-permuted (h1 GEMM A)
__device__ __half g_hidden_h[(size_t)MAXN * HDIM]; // fp16 hidden, k-permuted (h2 GEMM A)
__device__ __half g_w1h[HDIM * D];               // fp16 w1, k-permuted
__device__ __half g_w2h[D * HDIM];               // fp16 w2, k-permuted
__device__ int    g_row_start[MAXN + 1];

// k-permutation within each 16-k block
__device__ __host__ __forceinline__ int kperm_src(int pos) {
    int q = pos >> 2, s = pos & 3;
    return (q << 1) + ((s >> 1) << 3) + (s & 1);
}

// ------- merged init: CSR offsets + weight conversion (grid-stride both) -------
__global__ void k_init(const int* __restrict__ dst, int E, int Nc,
                       const float* __restrict__ w1, const float* __restrict__ w2) {
    int i = blockIdx.x * blockDim.x + threadIdx.x;
    if (i <= E) {
        int cur  = (i == E) ? Nc : dst[i];
        int prev = (i == 0) ? -1 : dst[i - 1];
        for (int n = prev + 1; n <= cur; n++) g_row_start[n] = i;
    }
    if (i < HDIM * D) {
        {   // w1: [HDIM][128]
            int row = i >> 7, pos = i & 127;
            int src = (pos & ~15) + kperm_src(pos & 15);
            g_w1h[i] = __float2half_rn(w1[(row << 7) + src]);
        }
        {   // w2: [D][512]
            int row = i >> 9, pos = i & 511;
            int src = (pos & ~15) + kperm_src(pos & 15);
            g_w2h[i] = __float2half_rn(w2[(row << 9) + src]);
        }
    }
}

// ---------------- helpers ----------------
__device__ __forceinline__ void mma_f16(float (&c)[4],
                                        const uint32_t (&a)[4],
                                        const uint32_t (&b)[2]) {
    asm volatile(
        "mma.sync.aligned.m16n8k16.row.col.f32.f16.f16.f32 "
        "{%0,%1,%2,%3}, {%4,%5,%6,%7}, {%8,%9}, {%0,%1,%2,%3};"
        : "+f"(c[0]), "+f"(c[1]), "+f"(c[2]), "+f"(c[3])
        : "r"(a[0]), "r"(a[1]), "r"(a[2]), "r"(a[3]), "r"(b[0]), "r"(b[1]));
}
__device__ __forceinline__ void cp16(uint32_t s, const void* g, int sz) {
    asm volatile("cp.async.ca.shared.global [%0], [%1], 16, %2;" :: "r"(s), "l"(g), "r"(sz));
}
#define CP_COMMIT() asm volatile("cp.async.commit_group;")
template <int N> __device__ __forceinline__ void cp_wait() {
    asm volatile("cp.async.wait_group %0;" :: "n"(N));
}

// ========== fp16 convert-staging core (gemm_z): fp32 in, cvt while staging ==========
template <int KDIM>
__device__ __forceinline__ void mma_core_cvt_h(
    const float* __restrict__ A, const float* __restrict__ B,
    int Nrows, int row0, int col0,
    float (&acc)[2][8][4], char* As, char* Bs)
{
    const int tid  = threadIdx.x;
    const int wid  = tid >> 5, lane = tid & 31;
    const int wm = wid >> 1, wn = wid & 1;
    const int lr = lane >> 2, q8 = (lane & 3) << 3;
    const int srow = tid >> 1;
    const int skq  = (tid & 1) * 8;
    const bool va = (row0 + srow) < Nrows;
    const float* Ap = A + (size_t)(row0 + srow) * KDIM + skq;
    const float* Bp = B + (size_t)(col0 + srow) * KDIM + skq;
    const float4 f40 = make_float4(0.f, 0.f, 0.f, 0.f);
    char* asw = As + srow * 32 + (tid & 1) * 4;
    char* bsw = Bs + srow * 32 + (tid & 1) * 4;

    float4 pa0 = va ? *(const float4*)(Ap)     : f40;
    float4 pa1 = va ? *(const float4*)(Ap + 4) : f40;
    float4 pb0 = *(const float4*)(Bp);
    float4 pb1 = *(const float4*)(Bp + 4);

    constexpr int NT = KDIM / 16;
    #pragma unroll 1
    for (int kt = 0; kt < NT; kt++) {
        *(__half2*)(asw +  0) = __floats2half2_rn(pa0.x, pa0.y);
        *(__half2*)(asw +  8) = __floats2half2_rn(pa0.z, pa0.w);
        *(__half2*)(asw + 16) = __floats2half2_rn(pa1.x, pa1.y);
        *(__half2*)(asw + 24) = __floats2half2_rn(pa1.z, pa1.w);
        *(__half2*)(bsw +  0) = __floats2half2_rn(pb0.x, pb0.y);
        *(__half2*)(bsw +  8) = __floats2half2_rn(pb0.z, pb0.w);
        *(__half2*)(bsw + 16) = __floats2half2_rn(pb1.x, pb1.y);
        *(__half2*)(bsw + 24) = __floats2half2_rn(pb1.z, pb1.w);
        __syncthreads();

        if (kt + 1 < NT) {
            int ko = (kt + 1) * 16;
            pa0 = va ? *(const float4*)(Ap + ko)     : f40;
            pa1 = va ? *(const float4*)(Ap + ko + 4) : f40;
            pb0 = *(const float4*)(Bp + ko);
            pb1 = *(const float4*)(Bp + ko + 4);
        }
        uint32_t af[2][4];
        #pragma unroll
        for (int mf = 0; mf < 2; mf++) {
            int r = wm * 32 + mf * 16 + lr;
            uint2 lo = *(const uint2*)(As + r * 32 + q8);
            uint2 hi = *(const uint2*)(As + (r + 8) * 32 + q8);
            af[mf][0] = lo.x; af[mf][1] = hi.x;
            af[mf][2] = lo.y; af[mf][3] = hi.y;
        }
        #pragma unroll
        for (int nf = 0; nf < 8; nf++) {
            int n = wn * 64 + nf * 8 + lr;
            uint2 bv = *(const uint2*)(Bs + n * 32 + q8);
            uint32_t bf[2] = {bv.x, bv.y};
            mma_f16(acc[0][nf], af[0], bf);
            mma_f16(acc[1][nf], af[1], bf);
        }
        __syncthreads();
    }
}

// ========== fp16 pipelined core (k-permuted operands, cp.async, 3-stage) ==========
template <int KDIM>
__device__ __forceinline__ void mma_core_h(
    const __half* __restrict__ A, const __half* __restrict__ B,
    int Nrows, int row0, int col0,
    float (&acc)[2][8][4], char* SA, char* SB)
{
    const int tid  = threadIdx.x;
    const int wid  = tid >> 5, lane = tid & 31;
    const int wm = wid >> 1, wn = wid & 1;
    const int lr = lane >> 2, q8 = (lane & 3) << 3;
    const int srow = tid >> 1;
    const int sk32 = (tid & 1) << 5;
    const int swz  = ((srow >> 1) & 1) << 5;
    const int szA  = ((row0 + srow) < Nrows) ? 16 : 0;
    const __half* Ap = A + (size_t)(row0 + srow) * KDIM + (tid & 1) * 16;
    const __half* Bp = B + (size_t)(col0 + srow) * KDIM + (tid & 1) * 16;
    uint32_t sa = (uint32_t)__cvta_generic_to_shared(SA);
    uint32_t sb = (uint32_t)__cvta_generic_to_shared(SB);
    const uint32_t so0 = (uint32_t)(srow * 64 + (sk32 ^ swz));
    constexpr int NT = KDIM / 32;

    auto stage = [&](int st, int kt) {
        uint32_t ao = sa + (uint32_t)st * 8192u;
        uint32_t bo = sb + (uint32_t)st * 8192u;
        const __half* a = Ap + kt * 32;
        const __half* b = Bp + kt * 32;
        cp16(ao + so0,      a,     szA);
        cp16(ao + so0 + 16, a + 8, szA);
        cp16(bo + so0,      b,     16);
        cp16(bo + so0 + 16, b + 8, 16);
        CP_COMMIT();
    };
    stage(0, 0);
    stage(1, 1 < NT ? 1 : 0);

    #pragma unroll 1
    for (int kt = 0; kt < NT; kt++) {
        if (kt + 1 < NT) cp_wait<1>(); else cp_wait<0>();
        __syncthreads();
        if (kt + 2 < NT) stage((kt + 2) % 3, kt + 2);
        const char* as = SA + (kt % 3) * 8192;
        const char* bs = SB + (kt % 3) * 8192;
        #pragma unroll
        for (int ks = 0; ks < 2; ks++) {
            const int cb = (ks << 5) + q8;
            uint32_t af[2][4];
            #pragma unroll
            for (int mf = 0; mf < 2; mf++) {
                int r  = wm * 32 + mf * 16 + lr;
                int r2 = r + 8;
                uint2 lo = *(const uint2*)(as + r  * 64 + (cb ^ (((r  >> 1) & 1) << 5)));
                uint2 hi = *(const uint2*)(as + r2 * 64 + (cb ^ (((r2 >> 1) & 1) << 5)));
                af[mf][0] = lo.x; af[mf][1] = hi.x;
                af[mf][2] = lo.y; af[mf][3] = hi.y;
            }
            #pragma unroll
            for (int nf = 0; nf < 8; nf++) {
                int n = wn * 64 + nf * 8 + lr;
                uint2 bv = *(const uint2*)(bs + n * 64 + (cb ^ (((n >> 1) & 1) << 5)));
                uint32_t bf[2] = {bv.x, bv.y};
                mma_f16(acc[0][nf], af[0], bf);
                mma_f16(acc[1][nf], af[1], bf);
            }
        }
    }
    __syncthreads();
}

// ------- z = s @ W_fc^T (fp16 MMA, stored fp16), fused w = exp(leaky_relu(z @ a)) -------
__global__ void __launch_bounds__(256, 2)
k_gemm_z(const float* __restrict__ s, const float* __restrict__ Wfc,
         const float* __restrict__ a_attn, int Nrows) {
    __shared__ __align__(16) char As[128 * 32], Bs[128 * 32];
    __shared__ float zap[2][128];
    float acc[2][8][4] = {};
    const int row0 = blockIdx.x * 128;
    mma_core_cvt_h<D>(s, Wfc, Nrows, row0, 0, acc, As, Bs);
    const int lane = threadIdx.x & 31, wid = threadIdx.x >> 5;
    const int wm = wid >> 1, wn = wid & 1;
    const int lr = lane >> 2, lc2 = (lane & 3) * 2;
    float2 av[8];
    #pragma unroll
    for (int nf = 0; nf < 8; nf++)
        av[nf] = *(const float2*)&a_attn[wn * 64 + nf * 8 + lc2];
    #pragma unroll
    for (int mf = 0; mf < 2; mf++)
        #pragma unroll
        for (int cp = 0; cp < 2; cp++) {
            int rl = wm * 32 + mf * 16 + lr + cp * 8;
            int r  = row0 + rl;
            float p = 0.f;
            #pragma unroll
            for (int nf = 0; nf < 8; nf++) {
                float z0 = acc[mf][nf][cp * 2], z1 = acc[mf][nf][cp * 2 + 1];
                p += z0 * av[nf].x + z1 * av[nf].y;
                if (r < Nrows) {
                    *(__half2*)&g_zh[(size_t)r * D + wn * 64 + nf * 8 + lc2] =
                        __floats2half2_rn(z0, z1);
                }
            }
            p += __shfl_xor_sync(0xffffffffu, p, 1);
            p += __shfl_xor_sync(0xffffffffu, p, 2);
            if ((lane & 3) == 0) zap[wn][rl] = p;
        }
    __syncthreads();
    if (wn == 0 && (lane & 3) == 0) {
        #pragma unroll
        for (int mf = 0; mf < 2; mf++)
            #pragma unroll
            for (int cp = 0; cp < 2; cp++) {
                int rl = wm * 32 + mf * 16 + lr + cp * 8;
                int r  = row0 + rl;
                if (r < Nrows) {
                    float e = zap[0][rl] + zap[1][rl];
                    e = e > 0.f ? e : 0.01f * e;
                    g_w[r] = __expf(e);
                }
            }
    }
}

// ------- warp-per-node aggregation (fp16 z, simple x2 unroll — R14 form) -------
__global__ void __launch_bounds__(256)
k_aggregate(const float* __restrict__ c, const int* __restrict__ src, int Nc) {
    int gw   = (blockIdx.x * blockDim.x + threadIdx.x) >> 5;
    int lane = threadIdx.x & 31;
    if (gw >= Nc) return;
    int beg = g_row_start[gw], end = g_row_start[gw + 1];
    float4 A0 = make_float4(0.f, 0.f, 0.f, 0.f);
    float4 A1 = make_float4(0.f, 0.f, 0.f, 0.f);
    float d0 = 0.f, d1 = 0.f;
    const uint2* zb = (const uint2*)g_zh + lane;   // row stride = 32 uint2
    int i = beg;
    for (; i + 2 <= end; i += 2) {
        int s0 = __ldg(&src[i]);
        int s1 = __ldg(&src[i + 1]);
        float w0 = g_w[s0];
        float w1 = g_w[s1];
        uint2 u0 = __ldg(zb + (size_t)s0 * 32);
        uint2 u1 = __ldg(zb + (size_t)s1 * 32);
        float2 l0 = __half22float2(*(const __half2*)&u0.x);
        float2 h0 = __half22float2(*(const __half2*)&u0.y);
        float2 l1 = __half22float2(*(const __half2*)&u1.x);
        float2 h1 = __half22float2(*(const __half2*)&u1.y);
        d0 += w0; d1 += w1;
        A0.x += w0 * l0.x; A0.y += w0 * l0.y; A0.z += w0 * h0.x; A0.w += w0 * h0.y;
        A1.x += w1 * l1.x; A1.y += w1 * l1.y; A1.z += w1 * h1.x; A1.w += w1 * h1.y;
    }
    if (i < end) {
        int s0 = __ldg(&src[i]);
        float w0 = g_w[s0];
        uint2 u0 = __ldg(zb + (size_t)s0 * 32);
        float2 l0 = __half22float2(*(const __half2*)&u0.x);
        float2 h0 = __half22float2(*(const __half2*)&u0.y);
        d0 += w0;
        A0.x += w0 * l0.x; A0.y += w0 * l0.y; A0.z += w0 * h0.x; A0.w += w0 * h0.y;
    }
    float4 A;
    A.x = A0.x + A1.x; A.y = A0.y + A1.y;
    A.z = A0.z + A1.z; A.w = A0.w + A1.w;
    if (beg < end) {
        float inv = 1.f / (d0 + d1);
        A.x *= inv; A.y *= inv; A.z *= inv; A.w *= inv;
    }
    float4 cv = *(const float4*)&c[(size_t)gw * D + lane * 4];
    float4 h;
    h.x = (A.x > 0.f ? A.x : __expf(A.x) - 1.f) + cv.x;
    h.y = (A.y > 0.f ? A.y : __expf(A.y) - 1.f) + cv.y;
    h.z = (A.z > 0.f ? A.z : __expf(A.z) - 1.f) + cv.z;
    h.w = (A.w > 0.f ? A.w : __expf(A.w) - 1.f) + cv.w;
    *(float4*)&g_hc[(size_t)gw * D + lane * 4] = h;
    // permuted fp16 write for the h1 GEMM A operand
    {
        int b = lane >> 2, r4 = lane & 3;
        int base1 = ((r4 & 1) << 3) | ((r4 >> 1) << 1);
        __half* dst = g_hc_h + (size_t)gw * D + b * 16;
        *(__half2*)(dst + base1)     = __floats2half2_rn(h.x, h.y);
        *(__half2*)(dst + base1 + 4) = __floats2half2_rn(h.z, h.w);
    }
}

// ---------------- hidden = relu(hc @ w1^T + b1), fp16 permuted out ----------------
__global__ void __launch_bounds__(256, 2)
k_gemm_h1(const float* __restrict__ b1, int Nrows) {
    __shared__ __align__(16) char SA[3 * 8192], SB[3 * 8192];
    float acc[2][8][4] = {};
    const int row0 = blockIdx.x * 128;
    const int col0 = blockIdx.y * 128;
    mma_core_h<D>(g_hc_h, g_w1h, Nrows, row0, col0, acc, SA, SB);
    const int lane = threadIdx.x & 31, wid = threadIdx.x >> 5;
    const int wm = wid >> 1, wn = wid & 1;
    const int lr = lane >> 2, lc2 = (lane & 3) * 2;
    float2 bb[8];
    #pragma unroll
    for (int nf = 0; nf < 8; nf++)
        bb[nf] = *(const float2*)&b1[col0 + wn * 64 + nf * 8 + lc2];
    #pragma unroll
    for (int mf = 0; mf < 2; mf++)
        #pragma unroll
        for (int cp = 0; cp < 2; cp++) {
            int r = row0 + wm * 32 + mf * 16 + lr + cp * 8;
            if (r >= Nrows) continue;
            #pragma unroll
            for (int nf = 0; nf < 8; nf++) {
                float vx = fmaxf(acc[mf][nf][cp * 2]     + bb[nf].x, 0.f);
                float vy = fmaxf(acc[mf][nf][cp * 2 + 1] + bb[nf].y, 0.f);
                int cc = col0 + wn * 64 + nf * 8 + lc2;
                int m  = (cc & 15) >> 1;
                int pp = ((m & 3) << 2) | ((m >> 2) << 1);
                *(__half2*)&g_hidden_h[(size_t)r * HDIM + (cc & ~15) + pp] =
                    __floats2half2_rn(vx, vy);
            }
        }
}

// --------- y = hidden @ w2^T + b2 + hc, LayerNorm -> out ---------
__global__ void __launch_bounds__(256, 2)
k_gemm_h2_ln(const float* __restrict__ b2,
             const float* __restrict__ lng, const float* __restrict__ lnb,
             float* __restrict__ out, int Nrows) {
    __shared__ __align__(16) char SA[3 * 8192], SB[3 * 8192];
    float acc[2][8][4] = {};
    const int row0 = blockIdx.x * 128;
    mma_core_h<HDIM>(g_hidden_h, g_w2h, Nrows, row0, 0, acc, SA, SB);
    float* part1 = (float*)SB;
    float* part2 = (float*)SB + 256;
    const int lane = threadIdx.x & 31, wid = threadIdx.x >> 5;
    const int wm = wid >> 1, wn = wid & 1;
    const int lr = lane >> 2, lc2 = (lane & 3) * 2;

    float2 bb[8], gg[8], be[8];
    #pragma unroll
    for (int nf = 0; nf < 8; nf++) {
        int cc = wn * 64 + nf * 8 + lc2;
        bb[nf] = *(const float2*)&b2[cc];
        gg[nf] = *(const float2*)&lng[cc];
        be[nf] = *(const float2*)&lnb[cc];
    }
    #pragma unroll
    for (int mf = 0; mf < 2; mf++)
        #pragma unroll
        for (int cp = 0; cp < 2; cp++) {
            int rl = wm * 32 + mf * 16 + lr + cp * 8;
            int r  = row0 + rl;
            bool ok = r < Nrows;
            float s1 = 0.f, s2 = 0.f;
            #pragma unroll
            for (int nf = 0; nf < 8; nf++) {
                float2 hv = ok ? *(const float2*)&g_hc[(size_t)r * D + wn * 64 + nf * 8 + lc2]
                               : make_float2(0.f, 0.f);
                float y0 = acc[mf][nf][cp * 2]     + bb[nf].x + hv.x;
                float y1 = acc[mf][nf][cp * 2 + 1] + bb[nf].y + hv.y;
                acc[mf][nf][cp * 2]     = y0;
                acc[mf][nf][cp * 2 + 1] = y1;
                s1 += y0 + y1;
                s2 += y0 * y0 + y1 * y1;
            }
            s1 += __shfl_xor_sync(0xffffffffu, s1, 1);
            s2 += __shfl_xor_sync(0xffffffffu, s2, 1);
            s1 += __shfl_xor_sync(0xffffffffu, s1, 2);
            s2 += __shfl_xor_sync(0xffffffffu, s2, 2);
            if ((lane & 3) == 0) {
                part1[wn * 128 + rl] = s1;
                part2[wn * 128 + rl] = s2;
            }
        }
    __syncthreads();
    #pragma unroll
    for (int mf = 0; mf < 2; mf++)
        #pragma unroll
        for (int cp = 0; cp < 2; cp++) {
            int rl = wm * 32 + mf * 16 + lr + cp * 8;
            int r  = row0 + rl;
            float s1 = part1[rl] + part1[128 + rl];
            float s2 = part2[rl] + part2[128 + rl];
            float mean = s1 * (1.f / D);
            float var  = s2 * (1.f / D) - mean * mean;
            float rstd = rsqrtf(var + LN_EPS);
            if (r >= Nrows) continue;
            #pragma unroll
            for (int nf = 0; nf < 8; nf++) {
                float2 v;
                v.x = (acc[mf][nf][cp * 2]     - mean) * rstd * gg[nf].x + be[nf].x;
                v.y = (acc[mf][nf][cp * 2 + 1] - mean) * rstd * gg[nf].y + be[nf].y;
                *(float2*)&out[(size_t)r * D + wn * 64 + nf * 8 + lc2] = v;
            }
        }
}

// ---------------- launch ----------------
extern "C" void kernel_launch(void* const* d_in, const int* in_sizes, int n_in,
                              void* d_out, int out_size) {
    const float* s      = (const float*)d_in[0];
    const float* c      = (const float*)d_in[1];
    const int*   src    = (const int*)d_in[2];
    const int*   dst    = (const int*)d_in[3];
    const float* Wfc    = (const float*)d_in[4];
    const float* a_attn = (const float*)d_in[5];
    const float* w1     = (const float*)d_in[6];
    const float* b1     = (const float*)d_in[7];
    const float* w2     = (const float*)d_in[8];
    const float* b2     = (const float*)d_in[9];
    const float* lng    = (const float*)d_in[10];
    const float* lnb    = (const float*)d_in[11];
    float* out = (float*)d_out;

    int Ns = in_sizes[0] / D;
    int Nc = in_sizes[1] / D;
    int E  = in_sizes[2];
    (void)n_in; (void)out_size;

    int init_n = (E + 1 > HDIM * D) ? E + 1 : HDIM * D;
    k_init<<<(init_n + 255) / 256, 256>>>(dst, E, Nc, w1, w2);
    k_gemm_z<<<(Ns + 127) / 128, 256>>>(s, Wfc, a_attn, Ns);
    k_aggregate<<<(Nc * 32 + 255) / 256, 256>>>(c, src, Nc);
    {
        dim3 g((Nc + 127) / 128, HDIM / 128);
        k_gemm_h1<<<g, 256>>>(b1, Nc);
    }
    k_gemm_h2_ln<<<(Nc + 127) / 128, 256>>>(b2, lng, lnb, out, Nc);
}